// round 7
// baseline (speedup 1.0000x reference)
#include <cuda_runtime.h>
#include <cuda_bf16.h>

#define NUM_BATCHES 16
#define CH 64
#define HID 16

// Scratch (alloc-free rule: __device__ globals).
// Zero-initialized at module load; se_mlp_kernel re-zeroes g_sum/g_cnt after
// consuming them, so the "zero at segsum entry" invariant holds on every
// graph replay without a dedicated zero kernel.
__device__ float g_sum[NUM_BATCHES * CH];
__device__ float g_cnt[NUM_BATCHES];
__device__ float g_gate[NUM_BATCHES * CH];

// ---------------------------------------------------------------------------
// Kernel 1: segment sum. Each warp owns a contiguous span of rows.
// batch_idx is GLOBALLY SORTED: if idx[row0]==idx[row1-1] the whole span is
// one segment -> branch-free float4 path, no per-row idx loads. At most 15
// of ~9500 warps straddle a boundary and take the slow per-row path.
//
// Fast path layout: lane = sub*16 + qc.  sub in {0,1} selects row within a
// pair, qc selects float4 (4 channels) within the row. One warp step reads
// 2 rows = 512B contiguous.
// ---------------------------------------------------------------------------
__global__ void __launch_bounds__(256)
se_segsum_kernel(const float* __restrict__ feats,
                 const int*   __restrict__ batch_idx,
                 int N, int rows_per_warp) {
    const int warp_id = (blockIdx.x * blockDim.x + threadIdx.x) >> 5;
    const int lane    = threadIdx.x & 31;

    long long row0 = (long long)warp_id * rows_per_warp;
    long long row1 = row0 + rows_per_warp;
    if (row0 >= N) return;
    if (row1 > N) row1 = N;

    const int b_first = __ldg(&batch_idx[row0]);
    const int b_last  = __ldg(&batch_idx[row1 - 1]);

    if (b_first == b_last) {
        // ---- Fast path: uniform segment, float4, 2 rows per warp step ----
        const float4* f4 = (const float4*)feats;   // row stride = 16 float4
        const int sub = lane >> 4;                  // row within pair
        const int qc  = lane & 15;                  // float4 within row

        float4 a0 = make_float4(0.f, 0.f, 0.f, 0.f);
        float4 a1 = make_float4(0.f, 0.f, 0.f, 0.f);

        long long r = row0;
        // unroll: 4 pairs = 8 rows per iter, 4 independent 16B loads per lane
        for (; r + 8 <= row1; r += 8) {
            #pragma unroll
            for (int u = 0; u < 8; u += 4) {
                float4 v0 = __ldcs(&f4[(r + u + sub) * 16 + qc]);
                float4 v1 = __ldcs(&f4[(r + u + 2 + sub) * 16 + qc]);
                a0.x += v0.x; a0.y += v0.y; a0.z += v0.z; a0.w += v0.w;
                a1.x += v1.x; a1.y += v1.y; a1.z += v1.z; a1.w += v1.w;
            }
        }
        for (; r + 2 <= row1; r += 2) {
            float4 v = __ldcs(&f4[(r + sub) * 16 + qc]);
            a0.x += v.x; a0.y += v.y; a0.z += v.z; a0.w += v.w;
        }
        if (r < row1 && sub == 0) {   // odd tail row: sub==0 lanes only
            float4 v = __ldcs(&f4[r * 16 + qc]);
            a0.x += v.x; a0.y += v.y; a0.z += v.z; a0.w += v.w;
        }
        a0.x += a1.x; a0.y += a1.y; a0.z += a1.z; a0.w += a1.w;

        // reduce across the two row-subs (lane l <-> l^16 hold same channels)
        a0.x += __shfl_xor_sync(0xffffffffu, a0.x, 16);
        a0.y += __shfl_xor_sync(0xffffffffu, a0.y, 16);
        a0.z += __shfl_xor_sync(0xffffffffu, a0.z, 16);
        a0.w += __shfl_xor_sync(0xffffffffu, a0.w, 16);

        if (sub == 0) {
            atomicAdd(&g_sum[b_first * CH + qc * 4 + 0], a0.x);
            atomicAdd(&g_sum[b_first * CH + qc * 4 + 1], a0.y);
            atomicAdd(&g_sum[b_first * CH + qc * 4 + 2], a0.z);
            atomicAdd(&g_sum[b_first * CH + qc * 4 + 3], a0.w);
        }
        if (lane == 0) atomicAdd(&g_cnt[b_first], (float)(row1 - row0));
    } else {
        // ---- Rare path: span crosses >=1 segment boundary (per-row) ----
        const float2* f2 = (const float2*)feats;   // row stride = 32 float2
        float2 acc = make_float2(0.0f, 0.0f);
        float  cnt = 0.0f;
        int cur_b = b_first;
        for (long long r = row0; r < row1; ++r) {
            int b = __ldg(&batch_idx[r]);
            if (b != cur_b) {
                atomicAdd(&g_sum[cur_b * CH + lane * 2 + 0], acc.x);
                atomicAdd(&g_sum[cur_b * CH + lane * 2 + 1], acc.y);
                if (lane == 0) atomicAdd(&g_cnt[cur_b], cnt);
                acc = make_float2(0.0f, 0.0f);
                cnt = 0.0f;
                cur_b = b;
            }
            float2 v = __ldcs(&f2[r * 32 + lane]);
            acc.x += v.x;
            acc.y += v.y;
            cnt += 1.0f;
        }
        atomicAdd(&g_sum[cur_b * CH + lane * 2 + 0], acc.x);
        atomicAdd(&g_sum[cur_b * CH + lane * 2 + 1], acc.y);
        if (lane == 0) atomicAdd(&g_cnt[cur_b], cnt);
    }
}

// ---------------------------------------------------------------------------
// Kernel 2: mean -> MLP -> sigmoid gate.  Single block, 256 threads.
// h[b][j]   = relu( sum_c mean[b][c] * W1[c][j] + b1[j] )      (16x16)
// gate[b][c]= sigmoid( sum_j h[b][j] * W2[j][c] + b2[c] )      (16x64)
// Epilogue re-zeroes g_sum/g_cnt so the next graph replay starts clean.
// ---------------------------------------------------------------------------
__global__ void se_mlp_kernel(const float* __restrict__ W1,
                              const float* __restrict__ b1,
                              const float* __restrict__ W2,
                              const float* __restrict__ b2) {
    __shared__ float s_mean[NUM_BATCHES * CH];
    __shared__ float s_h[NUM_BATCHES * HID];

    int t = threadIdx.x;  // 256 threads

    // mean
    for (int k = t; k < NUM_BATCHES * CH; k += 256) {
        int b = k / CH;
        float c = g_cnt[b];
        s_mean[k] = g_sum[k] / fmaxf(c, 1.0f);
    }
    __syncthreads();

    // g_sum/g_cnt fully consumed into s_mean -> reset for next replay
    for (int k = t; k < NUM_BATCHES * CH; k += 256) g_sum[k] = 0.0f;
    if (t < NUM_BATCHES) g_cnt[t] = 0.0f;

    // h: 256 threads = 16 b x 16 j
    {
        int b = t / HID;
        int j = t % HID;
        float s = b1[j];
        #pragma unroll
        for (int c = 0; c < CH; ++c)
            s += s_mean[b * CH + c] * W1[c * HID + j];
        s_h[b * HID + j] = fmaxf(s, 0.0f);
    }
    __syncthreads();

    // gate: 1024 outputs over 256 threads x 4
    #pragma unroll
    for (int it = 0; it < 4; ++it) {
        int k = t + it * 256;
        int b = k / CH;
        int c = k % CH;
        float s = b2[c];
        #pragma unroll
        for (int j = 0; j < HID; ++j)
            s += s_h[b * HID + j] * W2[j * CH + c];
        g_gate[k] = 1.0f / (1.0f + __expf(-s));
    }
}

// ---------------------------------------------------------------------------
// Kernel 3: out = feats * gate[batch_idx[row]], float4 vectorized.
// 16 float4 per row; 16 consecutive threads share one row (batch_idx
// broadcast within warp; gate table is 4KB, L2/L1-resident).
// ---------------------------------------------------------------------------
__global__ void __launch_bounds__(256)
se_gate_kernel(const float* __restrict__ feats,
               const int*   __restrict__ batch_idx,
               float* __restrict__ out,
               long long n_vec) {  // n_vec = N*64/4
    long long i = (long long)blockIdx.x * blockDim.x + threadIdx.x;
    if (i >= n_vec) return;

    long long row = i >> 4;          // 16 float4 per row
    int quad = (int)(i & 15);        // which float4 within the row
    int b = __ldg(&batch_idx[row]);

    const float4* f4 = (const float4*)feats;
    const float4* g4 = (const float4*)g_gate;
    float4 v = __ldcs(&f4[i]);       // streaming read (last touch)
    float4 g = __ldg(&g4[b * 16 + quad]);
    v.x *= g.x; v.y *= g.y; v.z *= g.z; v.w *= g.w;
    __stcs(&((float4*)out)[i], v);   // streaming store, never re-read
}

// ---------------------------------------------------------------------------
extern "C" void kernel_launch(void* const* d_in, const int* in_sizes, int n_in,
                              void* d_out, int out_size) {
    const float* feats     = (const float*)d_in[0];
    const int*   batch_idx = (const int*)d_in[1];
    const float* W1        = (const float*)d_in[2];
    const float* b1        = (const float*)d_in[3];
    const float* W2        = (const float*)d_in[4];
    const float* b2        = (const float*)d_in[5];
    float* out = (float*)d_out;

    const int N = in_sizes[1];  // batch_idx element count = number of rows

    // Kernel 1: segment sum. 1184 blocks x 256 thr = 9472 warps (~64/SM).
    // (g_sum/g_cnt are zero here: BSS-zero on first call, reset by
    //  se_mlp_kernel's epilogue on every subsequent replay.)
    const int blocks1 = 1184;
    const int warps = blocks1 * (256 / 32);
    const int rpw = (N + warps - 1) / warps;
    se_segsum_kernel<<<blocks1, 256>>>(feats, batch_idx, N, rpw);

    // Kernel 2: MLP + gate (+ scratch reset for next replay)
    se_mlp_kernel<<<1, 256>>>(W1, b1, W2, b2);

    // Kernel 3: gate multiply
    long long n_vec = (long long)N * CH / 4;
    int blocks3 = (int)((n_vec + 255) / 256);
    se_gate_kernel<<<blocks3, 256>>>(feats, batch_idx, out, n_vec);
}